// round 2
// baseline (speedup 1.0000x reference)
#include <cuda_runtime.h>
#include <cuda_bf16.h>

// Problem constants (fixed by setup_inputs)
#define NQ      512
#define NC      8000
#define DNUM    6
#define DCAT    20
#define NBINS   50
#define DENC    300        // DNUM*NBINS
#define DTOT    320        // DENC + DCAT
#define DOUT    10
#define CHUNK   1000
#define NCHUNKS 8
#define CPAD    1024       // padded chunk stride
#define NCPAD   (NCHUNKS * CPAD)   // 8192

#define TQ 16
#define TC 256
#define DK 16

#define PADVAL 1e7f
#define NEGBIG -1e30f

// Scratch (device globals; no allocations allowed)
__device__ float g_xT[DTOT][NQ];        // 640 KB, transposed query encodings
__device__ float g_cT[DTOT][NCPAD];     // 10.5 MB, transposed candidate encodings (chunk-padded)
__device__ int   g_y[NCPAD];            // candidate classes (pad -> 0, weight is 0 anyway)
__device__ float g_logits[NCHUNKS][NQ][DOUT];
__device__ float g_lse[NCHUNKS][NQ];

// ---------------------------------------------------------------------------
// Encoding kernels. Feature map: ceil((x - u*delta)/delta), done with explicit
// IEEE rn intrinsics (no FMA contraction) to match XLA's elementwise sequence.
// ---------------------------------------------------------------------------
__global__ void encode_x_kernel(const float* __restrict__ x_num,
                                const float* __restrict__ x_cat,
                                const float* __restrict__ delta,
                                const float* __restrict__ u) {
    int i = blockIdx.x * blockDim.x + threadIdx.x;
    if (i >= DTOT * NQ) return;
    int fd = i / NQ;
    int q  = i % NQ;
    float v;
    if (fd < DENC) {
        int j = fd / NBINS, b = fd % NBINS;
        float dl = delta[j * NBINS + b];
        float uu = u[j * NBINS + b];
        float su = __fmul_rn(uu, dl);
        v = ceilf(__fdiv_rn(__fsub_rn(x_num[q * DNUM + j], su), dl));
    } else {
        v = x_cat[q * DCAT + (fd - DENC)];
    }
    g_xT[fd][q] = v;
}

__global__ void encode_c_kernel(const float* __restrict__ c_num,
                                const float* __restrict__ c_cat,
                                const float* __restrict__ delta,
                                const float* __restrict__ u) {
    int i = blockIdx.x * blockDim.x + threadIdx.x;
    if (i >= DTOT * NCPAD) return;
    int fd  = i / NCPAD;
    int col = i % NCPAD;
    int ch  = col >> 10;          // /CPAD
    int idx = col & (CPAD - 1);
    float v;
    if (idx < CHUNK) {
        int c = ch * CHUNK + idx;
        if (fd < DENC) {
            int j = fd / NBINS, b = fd % NBINS;
            float dl = delta[j * NBINS + b];
            float uu = u[j * NBINS + b];
            float su = __fmul_rn(uu, dl);
            v = ceilf(__fdiv_rn(__fsub_rn(c_num[c * DNUM + j], su), dl));
        } else {
            v = c_cat[c * DCAT + (fd - DENC)];
        }
    } else {
        v = PADVAL;   // pad candidate: huge distance -> exp()==0, max unaffected
    }
    g_cT[fd][col] = v;
}

// Dtype-adaptive label loader. jax.random.randint(dtype=int64) silently yields
// int32 unless x64 is enabled, so the buffer may be either width. Detect by
// inspecting the raw words: if the labels are int64 (values 0..9, little
// endian), every odd 32-bit word of the first 32 elements is zero. For int32
// labels 0..9 the probability of that is 1e-32. Deterministic per run.
__global__ void encode_y_kernel(const void* __restrict__ cand_y_raw) {
    __shared__ int sh_is64;
    const int* p32 = (const int*)cand_y_raw;
    if (threadIdx.x == 0) {
        int all_odd_zero = 1;
        for (int i = 0; i < 32; ++i)
            if (p32[2 * i + 1] != 0) all_odd_zero = 0;
        sh_is64 = all_odd_zero;
    }
    __syncthreads();
    const int is64 = sh_is64;
    const long long* p64 = (const long long*)cand_y_raw;
    for (int col = threadIdx.x; col < NCPAD; col += blockDim.x) {
        int ch  = col >> 10;
        int idx = col & (CPAD - 1);
        int v = 0;
        if (idx < CHUNK) {
            int c = ch * CHUNK + idx;
            v = is64 ? (int)p64[c] : p32[c];
        }
        g_y[col] = v;
    }
}

// ---------------------------------------------------------------------------
// Main kernel: one block per (16-query tile, chunk). Block = (64, 4) threads.
// Each thread owns a 4q x 4c register tile; D streamed in DK slabs via smem.
// Per-thread logits[4][10] partials + online logsumexp; shuffle+shared reduce.
// ---------------------------------------------------------------------------
__global__ __launch_bounds__(256, 2) void nca_main_kernel() {
    const int tc  = threadIdx.x;                 // 0..63  (candidate dim)
    const int tq  = threadIdx.y;                 // 0..3   (query dim)
    const int lid = tq * 64 + tc;
    const int q0  = blockIdx.x * TQ;
    const int cb0 = blockIdx.y * CPAD;           // padded chunk base column

    __shared__ float x_sh[DTOT][TQ];             // 20 KB
    __shared__ float c_sh[DK][TC];               // 16 KB
    __shared__ float red[4][2][4][12];           // 1.5 KB reduce scratch

    // Load full query slab once
    for (int i = lid; i < DTOT * TQ; i += 256) {
        int d = i / TQ, q = i % TQ;
        x_sh[d][q] = g_xT[d][q0 + q];
    }

    float m[4], s[4], lg[4][10];
#pragma unroll
    for (int qi = 0; qi < 4; ++qi) {
        m[qi] = NEGBIG; s[qi] = 0.f;
#pragma unroll
        for (int k = 0; k < DOUT; ++k) lg[qi][k] = 0.f;
    }

    for (int t = 0; t < 4; ++t) {
        const int cbase = cb0 + t * TC;
        int yv[4];
#pragma unroll
        for (int ci = 0; ci < 4; ++ci) yv[ci] = g_y[cbase + tc * 4 + ci];

        float dist[4][4];
#pragma unroll
        for (int qi = 0; qi < 4; ++qi)
#pragma unroll
            for (int ci = 0; ci < 4; ++ci) dist[qi][ci] = 0.f;

        for (int d0 = 0; d0 < DTOT; d0 += DK) {
            __syncthreads();   // protect c_sh (and first pass: x_sh load)
            // stage DK x TC candidate slab (4096 floats = 1024 float4)
#pragma unroll
            for (int k = 0; k < 4; ++k) {
                int idx = lid + 256 * k;
                int dd = idx >> 6;
                int jj = (idx & 63) << 2;
                float4 v = *reinterpret_cast<const float4*>(&g_cT[d0 + dd][cbase + jj]);
                *reinterpret_cast<float4*>(&c_sh[dd][jj]) = v;
            }
            __syncthreads();
#pragma unroll
            for (int dd = 0; dd < DK; ++dd) {
                float4 xv = *reinterpret_cast<const float4*>(&x_sh[d0 + dd][tq * 4]);
                float4 cv = *reinterpret_cast<const float4*>(&c_sh[dd][tc * 4]);
                float xa[4] = {xv.x, xv.y, xv.z, xv.w};
                float ca[4] = {cv.x, cv.y, cv.z, cv.w};
#pragma unroll
                for (int qi = 0; qi < 4; ++qi)
#pragma unroll
                    for (int ci = 0; ci < 4; ++ci)
                        dist[qi][ci] += fabsf(xa[qi] - ca[ci]);
            }
        }

        // Epilogue for this 4x4 tile
#pragma unroll
        for (int ci = 0; ci < 4; ++ci) {
            int y = yv[ci];
#pragma unroll
            for (int qi = 0; qi < 4; ++qi) {
                float nd = -dist[qi][ci];
                float w  = __expf(nd);                 // pad: exp(-3e9) -> 0
                float mn = fmaxf(m[qi], nd);
                s[qi] = s[qi] * __expf(m[qi] - mn) + __expf(nd - mn);
                m[qi] = mn;
#pragma unroll
                for (int k = 0; k < DOUT; ++k)
                    lg[qi][k] += (y == k) ? w : 0.f;
            }
        }
    }

    // Warp-level reduce across 32 lanes (lanes == tc%32 consistently)
#pragma unroll
    for (int off = 16; off >= 1; off >>= 1) {
#pragma unroll
        for (int qi = 0; qi < 4; ++qi) {
            float mo = __shfl_xor_sync(0xffffffffu, m[qi], off);
            float so = __shfl_xor_sync(0xffffffffu, s[qi], off);
            float mn = fmaxf(m[qi], mo);
            s[qi] = s[qi] * __expf(m[qi] - mn) + so * __expf(mo - mn);
            m[qi] = mn;
#pragma unroll
            for (int k = 0; k < DOUT; ++k)
                lg[qi][k] += __shfl_xor_sync(0xffffffffu, lg[qi][k], off);
        }
    }

    __syncthreads();   // c_sh no longer needed; also orders red[] usage
    if ((tc & 31) == 0) {
        int h = tc >> 5;
#pragma unroll
        for (int qi = 0; qi < 4; ++qi) {
            red[tq][h][qi][0] = m[qi];
            red[tq][h][qi][1] = s[qi];
#pragma unroll
            for (int k = 0; k < DOUT; ++k) red[tq][h][qi][2 + k] = lg[qi][k];
        }
    }
    __syncthreads();
    if (tc == 0) {
#pragma unroll
        for (int qi = 0; qi < 4; ++qi) {
            float m0 = red[tq][0][qi][0], s0 = red[tq][0][qi][1];
            float m1 = red[tq][1][qi][0], s1 = red[tq][1][qi][1];
            float mn = fmaxf(m0, m1);
            float S  = s0 * __expf(m0 - mn) + s1 * __expf(m1 - mn);
            int q = q0 + tq * 4 + qi;
            g_lse[blockIdx.y][q] = mn + logf(S);
#pragma unroll
            for (int k = 0; k < DOUT; ++k)
                g_logits[blockIdx.y][q][k] = red[tq][0][qi][2 + k] + red[tq][1][qi][2 + k];
        }
    }
}

// ---------------------------------------------------------------------------
__global__ void finalize_kernel(float* __restrict__ out) {
    int i = blockIdx.x * blockDim.x + threadIdx.x;
    if (i >= NQ * DOUT) return;
    int q = i / DOUT, k = i % DOUT;
    float lsum = 0.f, lse = 0.f;
#pragma unroll
    for (int ch = 0; ch < NCHUNKS; ++ch) {
        lsum += g_logits[ch][q][k];
        lse  += g_lse[ch][q];
    }
    out[i] = logf(lsum + 1e-8f) - lse;
}

// ---------------------------------------------------------------------------
extern "C" void kernel_launch(void* const* d_in, const int* in_sizes, int n_in,
                              void* d_out, int out_size) {
    const float* x_num = (const float*)d_in[0];
    const float* x_cat = (const float*)d_in[1];
    const float* c_num = (const float*)d_in[2];
    const float* c_cat = (const float*)d_in[3];
    const void*  c_y   = (const void*)d_in[4];   // int32 or int64, detected on device
    const float* delta = (const float*)d_in[5];
    const float* u     = (const float*)d_in[6];
    float* out = (float*)d_out;

    encode_x_kernel<<<(DTOT * NQ + 255) / 256, 256>>>(x_num, x_cat, delta, u);
    encode_c_kernel<<<(DTOT * NCPAD + 255) / 256, 256>>>(c_num, c_cat, delta, u);
    encode_y_kernel<<<1, 256>>>(c_y);
    nca_main_kernel<<<dim3(NQ / TQ, NCHUNKS), dim3(64, 4)>>>();
    finalize_kernel<<<(NQ * DOUT + 255) / 256, 256>>>(out);
}

// round 4
// speedup vs baseline: 3.4792x; 3.4792x over previous
#include <cuda_runtime.h>
#include <cuda_bf16.h>

// Problem constants (fixed by setup_inputs)
#define NQ      512
#define NC      8000
#define DNUM    6
#define DCAT    20
#define NBINS   50
#define DOUT    10
#define CHUNK   1000
#define NCHUNKS 8
#define CPAD    1024
#define NCPAD   (NCHUNKS * CPAD)   // 8192

// Collapsed encoding: 6 bin-sum (G) dims + 20 cat dims + 2 zero pads = 28.
// Monotonicity of ceil((x - u*d)/d) in x makes sum|bin diffs| == |G(x)-G(c)|
// per feature, exactly (all bins are integers; G < 2^24 so fp32-exact).
#define DCOL 28

#define TQ 16
#define TC 256

#define PADVAL 1e7f
#define NEGBIG -1e30f

// Scratch (device globals; no allocations allowed)
__device__ float g_xT[DCOL][NQ];
__device__ float g_cT[DCOL][NCPAD];
__device__ int   g_y[NCPAD];
__device__ float g_logits[NCHUNKS][NQ][DOUT];
__device__ float g_lse[NCHUNKS][NQ];

// ---------------------------------------------------------------------------
// Fused encoder: candidate columns (chunk-padded), query columns, labels.
// Bin math uses explicit IEEE rn intrinsics to bit-match XLA's unfused ops.
// Label dtype is detected at runtime (jax randint(int64) silently yields
// int32 without x64): int64 labels 0..9 have all odd 32-bit words zero.
// ---------------------------------------------------------------------------
__global__ void encode_all_kernel(const float* __restrict__ x_num,
                                  const float* __restrict__ x_cat,
                                  const float* __restrict__ c_num,
                                  const float* __restrict__ c_cat,
                                  const void*  __restrict__ y_raw,
                                  const float* __restrict__ delta,
                                  const float* __restrict__ u) {
    __shared__ float s_d[DNUM * NBINS], s_u[DNUM * NBINS];
    __shared__ int sh_is64;
    const int lid = threadIdx.x;
    for (int i = lid; i < DNUM * NBINS; i += blockDim.x) {
        s_d[i] = delta[i];
        s_u[i] = u[i];
    }
    if (lid == 0) {
        const int* p32 = (const int*)y_raw;
        int z = 1;
        for (int i = 0; i < 32; ++i)
            if (p32[2 * i + 1] != 0) z = 0;
        sh_is64 = z;
    }
    __syncthreads();

    const int t = blockIdx.x * blockDim.x + lid;
    if (t < NCPAD) {
        const int c = t;
        const int ch = c >> 10, idx = c & (CPAD - 1);
        if (idx < CHUNK) {
            const int src = ch * CHUNK + idx;
#pragma unroll
            for (int j = 0; j < DNUM; ++j) {
                const float x = c_num[src * DNUM + j];
                float g = 0.f;
                for (int b = 0; b < NBINS; ++b) {
                    const float dl = s_d[j * NBINS + b];
                    const float uu = s_u[j * NBINS + b];
                    g = __fadd_rn(g, ceilf(__fdiv_rn(__fsub_rn(x, __fmul_rn(uu, dl)), dl)));
                }
                g_cT[j][c] = g;
            }
#pragma unroll
            for (int k = 0; k < DCAT; ++k) g_cT[DNUM + k][c] = c_cat[src * DCAT + k];
            g_cT[26][c] = 0.f;
            g_cT[27][c] = 0.f;
            const int* p32 = (const int*)y_raw;
            const long long* p64 = (const long long*)y_raw;
            g_y[c] = sh_is64 ? (int)p64[src] : p32[src];
        } else {
#pragma unroll
            for (int d = 0; d < DCOL; ++d) g_cT[d][c] = PADVAL;  // exp(-dist)=0, max unaffected
            g_y[c] = 0;
        }
    } else if (t < NCPAD + NQ) {
        const int q = t - NCPAD;
#pragma unroll
        for (int j = 0; j < DNUM; ++j) {
            const float x = x_num[q * DNUM + j];
            float g = 0.f;
            for (int b = 0; b < NBINS; ++b) {
                const float dl = s_d[j * NBINS + b];
                const float uu = s_u[j * NBINS + b];
                g = __fadd_rn(g, ceilf(__fdiv_rn(__fsub_rn(x, __fmul_rn(uu, dl)), dl)));
            }
            g_xT[j][q] = g;
        }
#pragma unroll
        for (int k = 0; k < DCAT; ++k) g_xT[DNUM + k][q] = x_cat[q * DCAT + k];
        g_xT[26][q] = 0.f;
        g_xT[27][q] = 0.f;
    }
}

// ---------------------------------------------------------------------------
// Main kernel: one block per (16-query tile, chunk). Block = (64, 4) threads.
// D=28 now, so the whole candidate sub-tile (28 x 256) is staged at once.
// Each thread owns a 4q x 4c register tile; online logsumexp + 10-class
// register partials; shuffle + shared reduce; exclusive output slots.
// ---------------------------------------------------------------------------
__global__ __launch_bounds__(256, 2) void nca_main_kernel() {
    const int tc  = threadIdx.x;                 // 0..63  (candidate dim)
    const int tq  = threadIdx.y;                 // 0..3   (query dim)
    const int lid = tq * 64 + tc;
    const int q0  = blockIdx.x * TQ;
    const int cb0 = blockIdx.y * CPAD;

    __shared__ float x_sh[DCOL][TQ];             // 1.75 KB
    __shared__ float c_sh[DCOL][TC];             // 28 KB
    __shared__ float red[4][2][4][12];

    for (int i = lid; i < DCOL * TQ; i += 256) {
        int d = i / TQ, q = i % TQ;
        x_sh[d][q] = g_xT[d][q0 + q];
    }

    float m[4], s[4], lg[4][10];
#pragma unroll
    for (int qi = 0; qi < 4; ++qi) {
        m[qi] = NEGBIG; s[qi] = 0.f;
#pragma unroll
        for (int k = 0; k < DOUT; ++k) lg[qi][k] = 0.f;
    }

    for (int t = 0; t < 4; ++t) {
        const int cbase = cb0 + t * TC;
        __syncthreads();   // protect c_sh reuse (1st iter: also x_sh store)
        // stage 28 x 256 candidate slab (7168 floats = 1792 float4)
#pragma unroll
        for (int k = 0; k < 7; ++k) {
            int idx = lid + 256 * k;
            int dd = idx >> 6;
            int jj = (idx & 63) << 2;
            *reinterpret_cast<float4*>(&c_sh[dd][jj]) =
                *reinterpret_cast<const float4*>(&g_cT[dd][cbase + jj]);
        }
        __syncthreads();

        int yv[4];
#pragma unroll
        for (int ci = 0; ci < 4; ++ci) yv[ci] = g_y[cbase + tc * 4 + ci];

        float dist[4][4];
#pragma unroll
        for (int qi = 0; qi < 4; ++qi)
#pragma unroll
            for (int ci = 0; ci < 4; ++ci) dist[qi][ci] = 0.f;

#pragma unroll
        for (int dd = 0; dd < DCOL; ++dd) {
            float4 xv = *reinterpret_cast<const float4*>(&x_sh[dd][tq * 4]);
            float4 cv = *reinterpret_cast<const float4*>(&c_sh[dd][tc * 4]);
            float xa[4] = {xv.x, xv.y, xv.z, xv.w};
            float ca[4] = {cv.x, cv.y, cv.z, cv.w};
#pragma unroll
            for (int qi = 0; qi < 4; ++qi)
#pragma unroll
                for (int ci = 0; ci < 4; ++ci)
                    dist[qi][ci] += fabsf(xa[qi] - ca[ci]);
        }

        // Epilogue for this 4x4 tile
#pragma unroll
        for (int ci = 0; ci < 4; ++ci) {
            int y = yv[ci];
#pragma unroll
            for (int qi = 0; qi < 4; ++qi) {
                float nd = -dist[qi][ci];
                float w  = __expf(nd);
                float mn = fmaxf(m[qi], nd);
                s[qi] = s[qi] * __expf(m[qi] - mn) + __expf(nd - mn);
                m[qi] = mn;
#pragma unroll
                for (int k = 0; k < DOUT; ++k)
                    lg[qi][k] += (y == k) ? w : 0.f;
            }
        }
    }

    // Warp-level reduce across 32 lanes
#pragma unroll
    for (int off = 16; off >= 1; off >>= 1) {
#pragma unroll
        for (int qi = 0; qi < 4; ++qi) {
            float mo = __shfl_xor_sync(0xffffffffu, m[qi], off);
            float so = __shfl_xor_sync(0xffffffffu, s[qi], off);
            float mn = fmaxf(m[qi], mo);
            s[qi] = s[qi] * __expf(m[qi] - mn) + so * __expf(mo - mn);
            m[qi] = mn;
#pragma unroll
            for (int k = 0; k < DOUT; ++k)
                lg[qi][k] += __shfl_xor_sync(0xffffffffu, lg[qi][k], off);
        }
    }

    __syncthreads();
    if ((tc & 31) == 0) {
        int h = tc >> 5;
#pragma unroll
        for (int qi = 0; qi < 4; ++qi) {
            red[tq][h][qi][0] = m[qi];
            red[tq][h][qi][1] = s[qi];
#pragma unroll
            for (int k = 0; k < DOUT; ++k) red[tq][h][qi][2 + k] = lg[qi][k];
        }
    }
    __syncthreads();
    if (tc == 0) {
#pragma unroll
        for (int qi = 0; qi < 4; ++qi) {
            float m0 = red[tq][0][qi][0], s0 = red[tq][0][qi][1];
            float m1 = red[tq][1][qi][0], s1 = red[tq][1][qi][1];
            float mn = fmaxf(m0, m1);
            float S  = s0 * __expf(m0 - mn) + s1 * __expf(m1 - mn);
            int q = q0 + tq * 4 + qi;
            g_lse[blockIdx.y][q] = mn + logf(S);
#pragma unroll
            for (int k = 0; k < DOUT; ++k)
                g_logits[blockIdx.y][q][k] = red[tq][0][qi][2 + k] + red[tq][1][qi][2 + k];
        }
    }
}

// ---------------------------------------------------------------------------
__global__ void finalize_kernel(float* __restrict__ out) {
    int i = blockIdx.x * blockDim.x + threadIdx.x;
    if (i >= NQ * DOUT) return;
    int q = i / DOUT, k = i % DOUT;
    float lsum = 0.f, lse = 0.f;
#pragma unroll
    for (int ch = 0; ch < NCHUNKS; ++ch) {
        lsum += g_logits[ch][q][k];
        lse  += g_lse[ch][q];
    }
    out[i] = logf(lsum + 1e-8f) - lse;
}

// ---------------------------------------------------------------------------
extern "C" void kernel_launch(void* const* d_in, const int* in_sizes, int n_in,
                              void* d_out, int out_size) {
    const float* x_num = (const float*)d_in[0];
    const float* x_cat = (const float*)d_in[1];
    const float* c_num = (const float*)d_in[2];
    const float* c_cat = (const float*)d_in[3];
    const void*  c_y   = (const void*)d_in[4];
    const float* delta = (const float*)d_in[5];
    const float* u     = (const float*)d_in[6];
    float* out = (float*)d_out;

    encode_all_kernel<<<(NCPAD + NQ + 255) / 256, 256>>>(
        x_num, x_cat, c_num, c_cat, c_y, delta, u);
    nca_main_kernel<<<dim3(NQ / TQ, NCHUNKS), dim3(64, 4)>>>();
    finalize_kernel<<<(NQ * DOUT + 255) / 256, 256>>>(out);
}

// round 5
// speedup vs baseline: 5.0153x; 1.4415x over previous
#include <cuda_runtime.h>
#include <cuda_bf16.h>

// Problem constants (fixed by setup_inputs)
#define NQ      512
#define NC      8000
#define DNUM    6
#define DCAT    20
#define NBINS   50
#define DOUT    10
#define CHUNK   1000
#define NCHUNKS 8
#define CPAD    1024
#define NCPAD   (NCHUNKS * CPAD)   // 8192
#define NENT    (NCPAD + NQ)       // 8704 padded entities (candidates then queries)

// Collapsed encoding: 6 bin-sum (G) dims + 20 cat dims + 2 zero pads = 28.
// Monotonicity of ceil((x - u*d)/d) in x makes sum|bin diffs| == |G(x)-G(c)|
// per feature, exactly (all bins are integers; G < 2^24 so fp32-exact).
#define DCOL 28

#define TQ 16
#define TC 256

#define PADVAL 1e7f
#define NEGBIG -1e30f

// Scratch (device globals; no allocations allowed)
__device__ float g_xT[DCOL][NQ];
__device__ float g_cT[DCOL][NCPAD];
__device__ int   g_y[NCPAD];
__device__ float g_logits[NCHUNKS][NQ][DOUT];
__device__ float g_lse[NCHUNKS][NQ];

// ---------------------------------------------------------------------------
// Parallel encoder.
//  Range A (NENT*DNUM threads): one thread = one (entity, feature) bin-sum.
//  Range B (NCPAD threads):     candidate cat transpose + pads + label.
//  Range C (NQ threads):        query cat transpose + pads.
// Bin math uses explicit IEEE rn intrinsics to bit-match XLA's unfused ops.
// Label dtype detected at runtime (jax randint(int64) silently yields int32
// without x64): int64 labels 0..9 have all odd 32-bit words zero.
// ---------------------------------------------------------------------------
#define RANGE_A (NENT * DNUM)            // 52224
#define RANGE_B NCPAD                    // 8192
#define RANGE_C NQ                       // 512
#define ENC_TOTAL (RANGE_A + RANGE_B + RANGE_C)

__global__ void encode_all_kernel(const float* __restrict__ x_num,
                                  const float* __restrict__ x_cat,
                                  const float* __restrict__ c_num,
                                  const float* __restrict__ c_cat,
                                  const void*  __restrict__ y_raw,
                                  const float* __restrict__ delta,
                                  const float* __restrict__ u) {
    __shared__ float s_d[DNUM * NBINS], s_u[DNUM * NBINS];
    const int lid = threadIdx.x;
    for (int i = lid; i < DNUM * NBINS; i += blockDim.x) {
        s_d[i] = delta[i];
        s_u[i] = u[i];
    }
    __syncthreads();

    const int t = blockIdx.x * blockDim.x + lid;
    if (t < RANGE_A) {
        const int j = t / NENT;          // feature 0..5
        const int e = t % NENT;          // padded entity
        if (e < NCPAD) {
            const int ch = e >> 10, idx = e & (CPAD - 1);
            if (idx < CHUNK) {
                const float x = c_num[(ch * CHUNK + idx) * DNUM + j];
                float g = 0.f;
#pragma unroll 10
                for (int b = 0; b < NBINS; ++b) {
                    const float dl = s_d[j * NBINS + b];
                    const float uu = s_u[j * NBINS + b];
                    g = __fadd_rn(g, ceilf(__fdiv_rn(__fsub_rn(x, __fmul_rn(uu, dl)), dl)));
                }
                g_cT[j][e] = g;
            } else {
                g_cT[j][e] = PADVAL;     // pad: exp(-dist)=0, max unaffected
            }
        } else {
            const int q = e - NCPAD;
            const float x = x_num[q * DNUM + j];
            float g = 0.f;
#pragma unroll 10
            for (int b = 0; b < NBINS; ++b) {
                const float dl = s_d[j * NBINS + b];
                const float uu = s_u[j * NBINS + b];
                g = __fadd_rn(g, ceilf(__fdiv_rn(__fsub_rn(x, __fmul_rn(uu, dl)), dl)));
            }
            g_xT[j][q] = g;
        }
    } else if (t < RANGE_A + RANGE_B) {
        const int c = t - RANGE_A;
        const int ch = c >> 10, idx = c & (CPAD - 1);
        if (idx < CHUNK) {
            const int src = ch * CHUNK + idx;
#pragma unroll
            for (int k = 0; k < DCAT; ++k) g_cT[DNUM + k][c] = c_cat[src * DCAT + k];
            g_cT[26][c] = 0.f;
            g_cT[27][c] = 0.f;
            const int* p32 = (const int*)y_raw;
            int z = 1;
#pragma unroll
            for (int i = 0; i < 32; ++i)
                if (p32[2 * i + 1] != 0) z = 0;
            const long long* p64 = (const long long*)y_raw;
            g_y[c] = z ? (int)p64[src] : p32[src];
        } else {
#pragma unroll
            for (int k = 0; k < DCAT + 2; ++k) g_cT[DNUM + k][c] = PADVAL;
            g_y[c] = 0;
        }
    } else if (t < ENC_TOTAL) {
        const int q = t - RANGE_A - RANGE_B;
#pragma unroll
        for (int k = 0; k < DCAT; ++k) g_xT[DNUM + k][q] = x_cat[q * DCAT + k];
        g_xT[26][q] = 0.f;
        g_xT[27][q] = 0.f;
    }
}

// ---------------------------------------------------------------------------
// Main kernel: one block per (16-query tile, chunk). Block = (64, 4) threads.
// Each thread owns a 4q x 4c register tile. Two-phase epilogue: per-tile max
// via FMNMX tree, ONE exp per pair shared between lse-sum and class partials
// (class partials kept in shifted space; un-shifted once before the reduce).
// ---------------------------------------------------------------------------
__global__ __launch_bounds__(256, 2) void nca_main_kernel() {
    const int tc  = threadIdx.x;                 // 0..63  (candidate dim)
    const int tq  = threadIdx.y;                 // 0..3   (query dim)
    const int lid = tq * 64 + tc;
    const int q0  = blockIdx.x * TQ;
    const int cb0 = blockIdx.y * CPAD;

    __shared__ float x_sh[DCOL][TQ];             // 1.75 KB
    __shared__ float c_sh[DCOL][TC];             // 28 KB
    __shared__ float red[4][2][4][12];

    for (int i = lid; i < DCOL * TQ; i += 256) {
        int d = i / TQ, q = i % TQ;
        x_sh[d][q] = g_xT[d][q0 + q];
    }

    float m[4], s[4], lg[4][10];                 // lg kept shifted by m[qi]
#pragma unroll
    for (int qi = 0; qi < 4; ++qi) {
        m[qi] = NEGBIG; s[qi] = 0.f;
#pragma unroll
        for (int k = 0; k < DOUT; ++k) lg[qi][k] = 0.f;
    }

    for (int t = 0; t < 4; ++t) {
        const int cbase = cb0 + t * TC;
        __syncthreads();   // protect c_sh reuse (1st iter: also x_sh store)
#pragma unroll
        for (int k = 0; k < 7; ++k) {
            int idx = lid + 256 * k;
            int dd = idx >> 6;
            int jj = (idx & 63) << 2;
            *reinterpret_cast<float4*>(&c_sh[dd][jj]) =
                *reinterpret_cast<const float4*>(&g_cT[dd][cbase + jj]);
        }
        __syncthreads();

        int yv[4];
#pragma unroll
        for (int ci = 0; ci < 4; ++ci) yv[ci] = g_y[cbase + tc * 4 + ci];

        float dist[4][4];
#pragma unroll
        for (int qi = 0; qi < 4; ++qi)
#pragma unroll
            for (int ci = 0; ci < 4; ++ci) dist[qi][ci] = 0.f;

#pragma unroll
        for (int dd = 0; dd < DCOL; ++dd) {
            float4 xv = *reinterpret_cast<const float4*>(&x_sh[dd][tq * 4]);
            float4 cv = *reinterpret_cast<const float4*>(&c_sh[dd][tc * 4]);
            float xa[4] = {xv.x, xv.y, xv.z, xv.w};
            float ca[4] = {cv.x, cv.y, cv.z, cv.w};
#pragma unroll
            for (int qi = 0; qi < 4; ++qi)
#pragma unroll
                for (int ci = 0; ci < 4; ++ci)
                    dist[qi][ci] += fabsf(xa[qi] - ca[ci]);
        }

        // Two-phase epilogue
#pragma unroll
        for (int qi = 0; qi < 4; ++qi) {
            float nd[4];
#pragma unroll
            for (int ci = 0; ci < 4; ++ci) nd[ci] = -dist[qi][ci];
            float tm = fmaxf(fmaxf(nd[0], nd[1]), fmaxf(nd[2], nd[3]));
            float mn = fmaxf(m[qi], tm);
            float corr = __expf(m[qi] - mn);
            m[qi] = mn;
            s[qi] *= corr;
#pragma unroll
            for (int k = 0; k < DOUT; ++k) lg[qi][k] *= corr;
#pragma unroll
            for (int ci = 0; ci < 4; ++ci) {
                float e = __expf(nd[ci] - mn);
                s[qi] += e;
                int y = yv[ci];
#pragma unroll
                for (int k = 0; k < DOUT; ++k)
                    lg[qi][k] += (y == k) ? e : 0.f;
            }
        }
    }

    // Un-shift class partials to true scale before summation reduce
#pragma unroll
    for (int qi = 0; qi < 4; ++qi) {
        float uw = __expf(m[qi]);
#pragma unroll
        for (int k = 0; k < DOUT; ++k) lg[qi][k] *= uw;
    }

    // Warp-level reduce across 32 lanes
#pragma unroll
    for (int off = 16; off >= 1; off >>= 1) {
#pragma unroll
        for (int qi = 0; qi < 4; ++qi) {
            float mo = __shfl_xor_sync(0xffffffffu, m[qi], off);
            float so = __shfl_xor_sync(0xffffffffu, s[qi], off);
            float mn = fmaxf(m[qi], mo);
            s[qi] = s[qi] * __expf(m[qi] - mn) + so * __expf(mo - mn);
            m[qi] = mn;
#pragma unroll
            for (int k = 0; k < DOUT; ++k)
                lg[qi][k] += __shfl_xor_sync(0xffffffffu, lg[qi][k], off);
        }
    }

    __syncthreads();
    if ((tc & 31) == 0) {
        int h = tc >> 5;
#pragma unroll
        for (int qi = 0; qi < 4; ++qi) {
            red[tq][h][qi][0] = m[qi];
            red[tq][h][qi][1] = s[qi];
#pragma unroll
            for (int k = 0; k < DOUT; ++k) red[tq][h][qi][2 + k] = lg[qi][k];
        }
    }
    __syncthreads();
    if (tc == 0) {
#pragma unroll
        for (int qi = 0; qi < 4; ++qi) {
            float m0 = red[tq][0][qi][0], s0 = red[tq][0][qi][1];
            float m1 = red[tq][1][qi][0], s1 = red[tq][1][qi][1];
            float mn = fmaxf(m0, m1);
            float S  = s0 * __expf(m0 - mn) + s1 * __expf(m1 - mn);
            int q = q0 + tq * 4 + qi;
            g_lse[blockIdx.y][q] = mn + logf(S);
#pragma unroll
            for (int k = 0; k < DOUT; ++k)
                g_logits[blockIdx.y][q][k] = red[tq][0][qi][2 + k] + red[tq][1][qi][2 + k];
        }
    }
}

// ---------------------------------------------------------------------------
__global__ void finalize_kernel(float* __restrict__ out) {
    int i = blockIdx.x * blockDim.x + threadIdx.x;
    if (i >= NQ * DOUT) return;
    int q = i / DOUT, k = i % DOUT;
    float lsum = 0.f, lse = 0.f;
#pragma unroll
    for (int ch = 0; ch < NCHUNKS; ++ch) {
        lsum += g_logits[ch][q][k];
        lse  += g_lse[ch][q];
    }
    out[i] = logf(lsum + 1e-8f) - lse;
}

// ---------------------------------------------------------------------------
extern "C" void kernel_launch(void* const* d_in, const int* in_sizes, int n_in,
                              void* d_out, int out_size) {
    const float* x_num = (const float*)d_in[0];
    const float* x_cat = (const float*)d_in[1];
    const float* c_num = (const float*)d_in[2];
    const float* c_cat = (const float*)d_in[3];
    const void*  c_y   = (const void*)d_in[4];
    const float* delta = (const float*)d_in[5];
    const float* u     = (const float*)d_in[6];
    float* out = (float*)d_out;

    encode_all_kernel<<<(ENC_TOTAL + 255) / 256, 256>>>(
        x_num, x_cat, c_num, c_cat, c_y, delta, u);
    nca_main_kernel<<<dim3(NQ / TQ, NCHUNKS), dim3(64, 4)>>>();
    finalize_kernel<<<(NQ * DOUT + 255) / 256, 256>>>(out);
}